// round 2
// baseline (speedup 1.0000x reference)
#include <cuda_runtime.h>

// Problem constants (fixed by the reference)
#define D_MODEL 2048
#define H_Q     32
#define H_KV    8
#define D_HEAD  64
#define G_RATIO 4          // H_Q / H_KV
#define BATCH   2
#define SEQ     2048
#define M_ROWS  (BATCH * SEQ)       // 4096
#define KV_DIM  (H_KV * D_HEAD)     // 512

// Scratch (allocation-free rule: __device__ globals)
__device__ float g_qh[M_ROWS * D_MODEL];   // projected Q   [B,S,H_Q,64]
__device__ float g_kh[M_ROWS * KV_DIM];    // projected K   [B,S,H_KV,64]
__device__ float g_vh[M_ROWS * KV_DIM];    // projected V   [B,S,H_KV,64]
__device__ float g_ctx[M_ROWS * D_MODEL];  // attention out [B,S,H_Q,64]

// ---------------------------------------------------------------------------
// Tiled fp32 SGEMM: C[M,N] = A[M,K] @ B[K,N], all row-major.
// 128x128 block tile, BK=8, 256 threads, 8x8 register micro-tile per thread.
// All dims used here are multiples of the tile sizes -> no bounds checks.
// ---------------------------------------------------------------------------
template <int BM, int BN, int BK, int TM, int TN>
__global__ __launch_bounds__(256) void sgemm_kernel(
    const float* __restrict__ A, const float* __restrict__ B,
    float* __restrict__ C, int M, int N, int K)
{
    __shared__ float As[BK][BM];   // A tile, transposed
    __shared__ float Bs[BK][BN];

    const int tid = threadIdx.x;                 // 0..255
    const int tx  = tid % (BN / TN);             // 0..15
    const int ty  = tid / (BN / TN);             // 0..15
    const int rowBase = blockIdx.y * BM;
    const int colBase = blockIdx.x * BN;

    // A tile load: 128 rows x 8 cols = 256 float4, one per thread
    const int aRow = tid >> 1;                   // 0..127
    const int aCol = (tid & 1) * 4;              // 0 or 4
    // B tile load: 8 rows x 128 cols = 256 float4, one per thread
    const int bRow = tid >> 5;                   // 0..7
    const int bCol = (tid & 31) * 4;             // 0..124

    const float* Aptr = A + (size_t)(rowBase + aRow) * K + aCol;
    const float* Bptr = B + (size_t)bRow * N + colBase + bCol;

    float acc[TM][TN] = {};
    float ar[TM], br[TN];

    for (int k0 = 0; k0 < K; k0 += BK) {
        float4 a4 = *(const float4*)(Aptr + k0);
        As[aCol + 0][aRow] = a4.x;
        As[aCol + 1][aRow] = a4.y;
        As[aCol + 2][aRow] = a4.z;
        As[aCol + 3][aRow] = a4.w;
        *(float4*)&Bs[bRow][bCol] = *(const float4*)(Bptr + (size_t)k0 * N);
        __syncthreads();

#pragma unroll
        for (int kk = 0; kk < BK; ++kk) {
#pragma unroll
            for (int i = 0; i < TM; i += 4) {
                float4 t = *(const float4*)&As[kk][ty * TM + i];
                ar[i] = t.x; ar[i + 1] = t.y; ar[i + 2] = t.z; ar[i + 3] = t.w;
            }
#pragma unroll
            for (int j = 0; j < TN; j += 4) {
                float4 t = *(const float4*)&Bs[kk][tx * TN + j];
                br[j] = t.x; br[j + 1] = t.y; br[j + 2] = t.z; br[j + 3] = t.w;
            }
#pragma unroll
            for (int i = 0; i < TM; ++i)
#pragma unroll
                for (int j = 0; j < TN; ++j)
                    acc[i][j] += ar[i] * br[j];
        }
        __syncthreads();
    }

#pragma unroll
    for (int i = 0; i < TM; ++i) {
        float* Crow = C + (size_t)(rowBase + ty * TM + i) * N + colBase + tx * TN;
#pragma unroll
        for (int j = 0; j < TN; j += 4) {
            float4 t = { acc[i][j], acc[i][j + 1], acc[i][j + 2], acc[i][j + 3] };
            *(float4*)(Crow + j) = t;
        }
    }
}

// ---------------------------------------------------------------------------
// Flash-style attention, fp32. One query row per thread.
// Block: 128 threads = 128 query rows. Grid: (SEQ/128, BATCH*H_Q).
// K/V streamed through shared memory in 64-key tiles; online softmax with
// 16-key chunks to bound register pressure (q[64] + o[64] + s[16]).
// Query head hq uses kv head hq / G_RATIO (matches reference reshape).
// ---------------------------------------------------------------------------
#define BM_ATT 128
#define BN_ATT 64
#define CH_ATT 16

__global__ __launch_bounds__(BM_ATT, 2) void attn_kernel()
{
    __shared__ float Ks[BN_ATT][D_HEAD];
    __shared__ float Vs[BN_ATT][D_HEAD];

    const int t    = threadIdx.x;            // 0..127
    const int bh   = blockIdx.y;             // 0..63
    const int b    = bh / H_Q;
    const int hq   = bh % H_Q;
    const int hkv  = hq / G_RATIO;
    const int row  = blockIdx.x * BM_ATT + t;   // query position in sequence

    // Load this thread's query row into registers
    float qreg[D_HEAD];
    const float* qp = g_qh + ((size_t)(b * SEQ + row) * D_MODEL) + hq * D_HEAD;
#pragma unroll
    for (int d = 0; d < D_HEAD; d += 4) {
        float4 v4 = *(const float4*)(qp + d);
        qreg[d] = v4.x; qreg[d + 1] = v4.y; qreg[d + 2] = v4.z; qreg[d + 3] = v4.w;
    }

    float o[D_HEAD] = {};
    float m = -1e30f, l = 0.0f;
    const float scale = 0.125f;   // 1/sqrt(64)

    for (int k0 = 0; k0 < SEQ; k0 += BN_ATT) {
        // Cooperative K/V tile load: 64x64 floats each, 8 float4 per thread
#pragma unroll
        for (int i = 0; i < 8; ++i) {
            int idx = i * BM_ATT + t;        // float4 index 0..1023
            int r   = idx >> 4;              // 16 float4 per 64-float row
            int c   = (idx & 15) * 4;
            size_t gaddr = ((size_t)(b * SEQ + k0 + r) * KV_DIM) + hkv * D_HEAD + c;
            *(float4*)&Ks[r][c] = *(const float4*)(g_kh + gaddr);
            *(float4*)&Vs[r][c] = *(const float4*)(g_vh + gaddr);
        }
        __syncthreads();

#pragma unroll 1
        for (int c0 = 0; c0 < BN_ATT; c0 += CH_ATT) {
            float s[CH_ATT];
            float cmax = -1e30f;
#pragma unroll 4
            for (int j = 0; j < CH_ATT; ++j) {
                float acc = 0.0f;
                const float4* kr = (const float4*)&Ks[c0 + j][0];
#pragma unroll
                for (int d4 = 0; d4 < D_HEAD / 4; ++d4) {
                    float4 kv = kr[d4];
                    acc += qreg[4 * d4 + 0] * kv.x;
                    acc += qreg[4 * d4 + 1] * kv.y;
                    acc += qreg[4 * d4 + 2] * kv.z;
                    acc += qreg[4 * d4 + 3] * kv.w;
                }
                s[j] = acc * scale;
                cmax = fmaxf(cmax, s[j]);
            }
            float mnew = fmaxf(m, cmax);
            float corr = __expf(m - mnew);
            l *= corr;
#pragma unroll
            for (int d = 0; d < D_HEAD; ++d) o[d] *= corr;
#pragma unroll 4
            for (int j = 0; j < CH_ATT; ++j) {
                float p = __expf(s[j] - mnew);
                l += p;
                const float4* vr = (const float4*)&Vs[c0 + j][0];
#pragma unroll
                for (int d4 = 0; d4 < D_HEAD / 4; ++d4) {
                    float4 vv = vr[d4];
                    o[4 * d4 + 0] += p * vv.x;
                    o[4 * d4 + 1] += p * vv.y;
                    o[4 * d4 + 2] += p * vv.z;
                    o[4 * d4 + 3] += p * vv.w;
                }
            }
            m = mnew;
        }
        __syncthreads();
    }

    const float inv_l = 1.0f / l;
    float* op = g_ctx + ((size_t)(b * SEQ + row) * D_MODEL) + hq * D_HEAD;
#pragma unroll
    for (int d = 0; d < D_HEAD; d += 4) {
        float4 v4 = { o[d] * inv_l, o[d + 1] * inv_l, o[d + 2] * inv_l, o[d + 3] * inv_l };
        *(float4*)(op + d) = v4;
    }
}

// ---------------------------------------------------------------------------
// Launch: 3 projection GEMMs -> attention -> output GEMM. Default stream,
// graph-capturable (kernel launches + symbol-address queries only).
// ---------------------------------------------------------------------------
extern "C" void kernel_launch(void* const* d_in, const int* in_sizes, int n_in,
                              void* d_out, int out_size)
{
    const float* q  = (const float*)d_in[0];
    const float* k  = (const float*)d_in[1];
    const float* v  = (const float*)d_in[2];
    const float* Wq = (const float*)d_in[3];
    const float* Wk = (const float*)d_in[4];
    const float* Wv = (const float*)d_in[5];
    const float* Wo = (const float*)d_in[6];
    float* out = (float*)d_out;

    float *qh, *kh, *vh, *ctx;
    cudaGetSymbolAddress((void**)&qh,  g_qh);
    cudaGetSymbolAddress((void**)&kh,  g_kh);
    cudaGetSymbolAddress((void**)&vh,  g_vh);
    cudaGetSymbolAddress((void**)&ctx, g_ctx);

    dim3 blk(256);
    // Q projection: [4096,2048] @ [2048,2048]
    sgemm_kernel<128, 128, 8, 8, 8>
        <<<dim3(D_MODEL / 128, M_ROWS / 128), blk>>>(q, Wq, qh, M_ROWS, D_MODEL, D_MODEL);
    // K projection: [4096,2048] @ [2048,512]
    sgemm_kernel<128, 128, 8, 8, 8>
        <<<dim3(KV_DIM / 128, M_ROWS / 128), blk>>>(k, Wk, kh, M_ROWS, KV_DIM, D_MODEL);
    // V projection
    sgemm_kernel<128, 128, 8, 8, 8>
        <<<dim3(KV_DIM / 128, M_ROWS / 128), blk>>>(v, Wv, vh, M_ROWS, KV_DIM, D_MODEL);
    // Attention
    attn_kernel<<<dim3(SEQ / BM_ATT, BATCH * H_Q), dim3(BM_ATT)>>>();
    // Output projection: [4096,2048] @ [2048,2048]
    sgemm_kernel<128, 128, 8, 8, 8>
        <<<dim3(D_MODEL / 128, M_ROWS / 128), blk>>>(ctx, Wo, out, M_ROWS, D_MODEL, D_MODEL);
}

// round 4
// speedup vs baseline: 1.5113x; 1.5113x over previous
#include <cuda_runtime.h>
#include <cstdint>

// Problem constants (fixed by the reference)
#define D_MODEL 2048
#define H_Q     32
#define H_KV    8
#define D_HEAD  64
#define G_RATIO 4          // H_Q / H_KV
#define BATCH   2
#define SEQ     2048
#define M_ROWS  (BATCH * SEQ)       // 4096
#define KV_DIM  (H_KV * D_HEAD)     // 512

// Scratch (allocation-free rule: __device__ globals)
__device__ float g_qh[M_ROWS * D_MODEL];   // projected Q   [B,S,H_Q,64]
__device__ float g_kh[M_ROWS * KV_DIM];    // projected K   [B,S,H_KV,64]
__device__ float g_vh[M_ROWS * KV_DIM];    // projected V   [B,S,H_KV,64]
__device__ float g_ctx[M_ROWS * D_MODEL];  // attention out [B,S,H_Q,64]

// ---------------------------------------------------------------------------
// tf32 helpers
// ---------------------------------------------------------------------------
__device__ __forceinline__ float to_tf32(float x) {
    float y;
    asm("cvt.rna.tf32.f32 %0, %1;" : "=f"(y) : "f"(x));   // round-to-nearest!
    return y;
}

__device__ __forceinline__ void mma_tf32_16x8x8(
    float& d0, float& d1, float& d2, float& d3,
    uint32_t a0, uint32_t a1, uint32_t a2, uint32_t a3,
    uint32_t b0, uint32_t b1)
{
    asm volatile(
        "mma.sync.aligned.m16n8k8.row.col.f32.tf32.tf32.f32 "
        "{%0,%1,%2,%3}, {%4,%5,%6,%7}, {%8,%9}, {%0,%1,%2,%3};"
        : "+f"(d0), "+f"(d1), "+f"(d2), "+f"(d3)
        : "r"(a0), "r"(a1), "r"(a2), "r"(a3), "r"(b0), "r"(b1));
}

// ---------------------------------------------------------------------------
// tf32 tensor-core GEMM: C[M,N] = A[M,K] @ B[K,N], row-major fp32 in/out.
// Block tile 128x128, BK=32, 256 threads = 8 warps laid out 2x4,
// each warp computes a 64x32 tile via m16n8k8 tf32 mma (4x4 mma tiles).
// Inputs are converted to tf32 (cvt.rna) while staging into SMEM.
// ---------------------------------------------------------------------------
#define GBM 128
#define GBN 128
#define GBK 32
#define A_PAD 4
#define B_PAD 4

__global__ __launch_bounds__(256, 2) void gemm_tf32_kernel(
    const float* __restrict__ A, const float* __restrict__ B,
    float* __restrict__ C, int M, int N, int K)
{
    __shared__ float As[GBM][GBK + A_PAD];   // [m][k]
    __shared__ float Bs[GBK][GBN + B_PAD];   // [k][n]

    const int tid  = threadIdx.x;
    const int warp = tid >> 5;
    const int lane = tid & 31;
    const int g    = lane >> 2;      // groupID           0..7
    const int c    = lane & 3;       // threadID_in_group 0..3

    const int wr = warp >> 2;        // 0..1  warp row
    const int wc = warp & 3;         // 0..3  warp col
    const int wmBase = wr * 64;      // warp tile origin inside block tile
    const int wnBase = wc * 32;

    const int rowBase = blockIdx.y * GBM;
    const int colBase = blockIdx.x * GBN;

    // Staging index precompute.
    // A tile: 128 rows x 32 cols = 1024 float4; 4 per thread.
    // B tile:  32 rows x 128 cols = 1024 float4; 4 per thread.
    float acc[4][4][4];
#pragma unroll
    for (int mi = 0; mi < 4; ++mi)
#pragma unroll
        for (int ni = 0; ni < 4; ++ni)
#pragma unroll
            for (int r = 0; r < 4; ++r) acc[mi][ni][r] = 0.0f;

    for (int k0 = 0; k0 < K; k0 += GBK) {
        // ---- stage A ----
#pragma unroll
        for (int j = 0; j < 4; ++j) {
            int f  = tid + j * 256;          // 0..1023
            int m  = f >> 3;                 // 0..127
            int kc = (f & 7) * 4;            // 0..28
            float4 v4 = *(const float4*)(A + (size_t)(rowBase + m) * K + k0 + kc);
            As[m][kc + 0] = to_tf32(v4.x);
            As[m][kc + 1] = to_tf32(v4.y);
            As[m][kc + 2] = to_tf32(v4.z);
            As[m][kc + 3] = to_tf32(v4.w);
        }
        // ---- stage B ----
#pragma unroll
        for (int j = 0; j < 4; ++j) {
            int f  = tid + j * 256;
            int kr = f >> 5;                 // 0..31
            int nc = (f & 31) * 4;           // 0..124
            float4 v4 = *(const float4*)(B + (size_t)(k0 + kr) * N + colBase + nc);
            Bs[kr][nc + 0] = to_tf32(v4.x);
            Bs[kr][nc + 1] = to_tf32(v4.y);
            Bs[kr][nc + 2] = to_tf32(v4.z);
            Bs[kr][nc + 3] = to_tf32(v4.w);
        }
        __syncthreads();

#pragma unroll
        for (int ks = 0; ks < GBK / 8; ++ks) {
            const int kb = ks * 8;
            uint32_t afr[4][4];
#pragma unroll
            for (int mi = 0; mi < 4; ++mi) {
                int r = wmBase + mi * 16;
                afr[mi][0] = __float_as_uint(As[r + g    ][kb + c    ]);
                afr[mi][1] = __float_as_uint(As[r + g + 8][kb + c    ]);
                afr[mi][2] = __float_as_uint(As[r + g    ][kb + c + 4]);
                afr[mi][3] = __float_as_uint(As[r + g + 8][kb + c + 4]);
            }
            uint32_t bfr[4][2];
#pragma unroll
            for (int ni = 0; ni < 4; ++ni) {
                int col = wnBase + ni * 8;
                bfr[ni][0] = __float_as_uint(Bs[kb + c    ][col + g]);
                bfr[ni][1] = __float_as_uint(Bs[kb + c + 4][col + g]);
            }
#pragma unroll
            for (int mi = 0; mi < 4; ++mi)
#pragma unroll
                for (int ni = 0; ni < 4; ++ni)
                    mma_tf32_16x8x8(acc[mi][ni][0], acc[mi][ni][1],
                                    acc[mi][ni][2], acc[mi][ni][3],
                                    afr[mi][0], afr[mi][1], afr[mi][2], afr[mi][3],
                                    bfr[ni][0], bfr[ni][1]);
        }
        __syncthreads();
    }

    // ---- write back ----
#pragma unroll
    for (int mi = 0; mi < 4; ++mi) {
        int r0 = rowBase + wmBase + mi * 16 + g;
#pragma unroll
        for (int ni = 0; ni < 4; ++ni) {
            int col = colBase + wnBase + ni * 8 + 2 * c;
            float2 lo = { acc[mi][ni][0], acc[mi][ni][1] };
            float2 hi = { acc[mi][ni][2], acc[mi][ni][3] };
            *(float2*)(C + (size_t)r0 * N + col)       = lo;
            *(float2*)(C + (size_t)(r0 + 8) * N + col) = hi;
        }
    }
}

// ---------------------------------------------------------------------------
// Flash-style attention, fp32 (unchanged from Round 1 — Round 3 target).
// ---------------------------------------------------------------------------
#define BM_ATT 128
#define BN_ATT 64
#define CH_ATT 16

__global__ __launch_bounds__(BM_ATT, 2) void attn_kernel()
{
    __shared__ float Ks[BN_ATT][D_HEAD];
    __shared__ float Vs[BN_ATT][D_HEAD];

    const int t    = threadIdx.x;            // 0..127
    const int bh   = blockIdx.y;             // 0..63
    const int b    = bh / H_Q;
    const int hq   = bh % H_Q;
    const int hkv  = hq / G_RATIO;
    const int row  = blockIdx.x * BM_ATT + t;

    float qreg[D_HEAD];
    const float* qp = g_qh + ((size_t)(b * SEQ + row) * D_MODEL) + hq * D_HEAD;
#pragma unroll
    for (int d = 0; d < D_HEAD; d += 4) {
        float4 v4 = *(const float4*)(qp + d);
        qreg[d] = v4.x; qreg[d + 1] = v4.y; qreg[d + 2] = v4.z; qreg[d + 3] = v4.w;
    }

    float o[D_HEAD] = {};
    float m = -1e30f, l = 0.0f;
    const float scale = 0.125f;

    for (int k0 = 0; k0 < SEQ; k0 += BN_ATT) {
#pragma unroll
        for (int i = 0; i < 8; ++i) {
            int idx = i * BM_ATT + t;
            int r   = idx >> 4;
            int cc  = (idx & 15) * 4;
            size_t gaddr = ((size_t)(b * SEQ + k0 + r) * KV_DIM) + hkv * D_HEAD + cc;
            *(float4*)&Ks[r][cc] = *(const float4*)(g_kh + gaddr);
            *(float4*)&Vs[r][cc] = *(const float4*)(g_vh + gaddr);
        }
        __syncthreads();

#pragma unroll 1
        for (int c0 = 0; c0 < BN_ATT; c0 += CH_ATT) {
            float s[CH_ATT];
            float cmax = -1e30f;
#pragma unroll 4
            for (int j = 0; j < CH_ATT; ++j) {
                float acc = 0.0f;
                const float4* kr = (const float4*)&Ks[c0 + j][0];
#pragma unroll
                for (int d4 = 0; d4 < D_HEAD / 4; ++d4) {
                    float4 kv = kr[d4];
                    acc += qreg[4 * d4 + 0] * kv.x;
                    acc += qreg[4 * d4 + 1] * kv.y;
                    acc += qreg[4 * d4 + 2] * kv.z;
                    acc += qreg[4 * d4 + 3] * kv.w;
                }
                s[j] = acc * scale;
                cmax = fmaxf(cmax, s[j]);
            }
            float mnew = fmaxf(m, cmax);
            float corr = __expf(m - mnew);
            l *= corr;
#pragma unroll
            for (int d = 0; d < D_HEAD; ++d) o[d] *= corr;
#pragma unroll 4
            for (int j = 0; j < CH_ATT; ++j) {
                float p = __expf(s[j] - mnew);
                l += p;
                const float4* vr = (const float4*)&Vs[c0 + j][0];
#pragma unroll
                for (int d4 = 0; d4 < D_HEAD / 4; ++d4) {
                    float4 vv = vr[d4];
                    o[4 * d4 + 0] += p * vv.x;
                    o[4 * d4 + 1] += p * vv.y;
                    o[4 * d4 + 2] += p * vv.z;
                    o[4 * d4 + 3] += p * vv.w;
                }
            }
            m = mnew;
        }
        __syncthreads();
    }

    const float inv_l = 1.0f / l;
    float* op = g_ctx + ((size_t)(b * SEQ + row) * D_MODEL) + hq * D_HEAD;
#pragma unroll
    for (int d = 0; d < D_HEAD; d += 4) {
        float4 v4 = { o[d] * inv_l, o[d + 1] * inv_l, o[d + 2] * inv_l, o[d + 3] * inv_l };
        *(float4*)(op + d) = v4;
    }
}

// ---------------------------------------------------------------------------
// Launch
// ---------------------------------------------------------------------------
extern "C" void kernel_launch(void* const* d_in, const int* in_sizes, int n_in,
                              void* d_out, int out_size)
{
    const float* q  = (const float*)d_in[0];
    const float* k  = (const float*)d_in[1];
    const float* v  = (const float*)d_in[2];
    const float* Wq = (const float*)d_in[3];
    const float* Wk = (const float*)d_in[4];
    const float* Wv = (const float*)d_in[5];
    const float* Wo = (const float*)d_in[6];
    float* out = (float*)d_out;

    float *qh, *kh, *vh, *ctx;
    cudaGetSymbolAddress((void**)&qh,  g_qh);
    cudaGetSymbolAddress((void**)&kh,  g_kh);
    cudaGetSymbolAddress((void**)&vh,  g_vh);
    cudaGetSymbolAddress((void**)&ctx, g_ctx);

    dim3 blk(256);
    gemm_tf32_kernel<<<dim3(D_MODEL / GBN, M_ROWS / GBM), blk>>>(q, Wq, qh, M_ROWS, D_MODEL, D_MODEL);
    gemm_tf32_kernel<<<dim3(KV_DIM / GBN, M_ROWS / GBM), blk>>>(k, Wk, kh, M_ROWS, KV_DIM, D_MODEL);
    gemm_tf32_kernel<<<dim3(KV_DIM / GBN, M_ROWS / GBM), blk>>>(v, Wv, vh, M_ROWS, KV_DIM, D_MODEL);
    attn_kernel<<<dim3(SEQ / BM_ATT, BATCH * H_Q), dim3(BM_ATT)>>>();
    gemm_tf32_kernel<<<dim3(D_MODEL / GBN, M_ROWS / GBM), blk>>>(ctx, Wo, out, M_ROWS, D_MODEL, D_MODEL);
}